// round 3
// baseline (speedup 1.0000x reference)
#include <cuda_runtime.h>
#include <math.h>

#define B_  64
#define LQ  32
#define O_  128
#define LK  256
#define D_  128

// Scratch (device globals: allocation-free per harness rules)
__device__ float g_qn[B_ * LQ * D_];   // 1 MB  normalized q
__device__ float g_kn[O_ * LK * D_];   // 16 MB normalized k
__device__ int   g_q_active[B_];       // 1 if batch has NO masked query token
__device__ int   g_mask_mode;          // 0=int32, 1=uint8, 2=float32

// Mode-dispatched mask read (True = padding/masked)
__device__ __forceinline__ bool mask_at(const void* buf, int idx, int mode) {
    if (mode == 0) return ((const int*)buf)[idx] != 0;
    if (mode == 2) return ((const float*)buf)[idx] != 0.0f;
    return ((const unsigned char*)buf)[idx] != 0;
}

// ---------------------------------------------------------------------------
// Kernel 0: sniff mask dtype from the first 2048 BYTES of q_mask (safe for
// all candidate dtypes: uint8 buffer is exactly 2048B, int32/f32 are larger).
// ---------------------------------------------------------------------------
__global__ void detect_mask_kernel(const unsigned int* __restrict__ qm_words) {
    // single warp
    int l = threadIdx.x;
    bool ok_i32 = true, ok_f32 = true;
    for (int i = l; i < 512; i += 32) {
        unsigned int w = qm_words[i];
        if (w > 1u) ok_i32 = false;
        if (w != 0u && w != 0x3F800000u) ok_f32 = false;
    }
    unsigned bi = __ballot_sync(0xffffffffu, ok_i32);
    unsigned bf = __ballot_sync(0xffffffffu, ok_f32);
    if (l == 0) {
        int mode;
        if (bi == 0xffffffffu)      mode = 0;  // int32 0/1
        else if (bf == 0xffffffffu) mode = 2;  // float32 0.0/1.0
        else                        mode = 1;  // uint8
        g_mask_mode = mode;
    }
}

// ---------------------------------------------------------------------------
// Kernel 1: L2-normalize all q rows and k rows (warp per 128-float row).
// ---------------------------------------------------------------------------
__global__ void norm_kernel(const float* __restrict__ q,
                            const float* __restrict__ k) {
    int gw   = (blockIdx.x * blockDim.x + threadIdx.x) >> 5;
    int lane = threadIdx.x & 31;
    const int nq = B_ * LQ;
    const int nrows = nq + O_ * LK;
    if (gw >= nrows) return;
    const float* src;
    float* dst;
    int row;
    if (gw < nq) { src = q; dst = g_qn; row = gw; }
    else         { src = k; dst = g_kn; row = gw - nq; }
    float4 v = ((const float4*)(src + (size_t)row * D_))[lane];
    float ss = v.x * v.x + v.y * v.y + v.z * v.z + v.w * v.w;
    #pragma unroll
    for (int o = 16; o; o >>= 1) ss += __shfl_xor_sync(0xffffffffu, ss, o);
    float rn = 1.0f / fmaxf(sqrtf(ss), 1e-12f);
    float4 r = make_float4(v.x * rn, v.y * rn, v.z * rn, v.w * rn);
    ((float4*)(dst + (size_t)row * D_))[lane] = r;
}

// ---------------------------------------------------------------------------
// Kernel 2: per-batch "no masked query token" flag.
// ---------------------------------------------------------------------------
__global__ void qactive_kernel(const void* __restrict__ qm) {
    int b = blockIdx.x;
    int l = threadIdx.x;
    int mode = g_mask_mode;
    bool m = mask_at(qm, b * LQ + l, mode);
    unsigned bal = __ballot_sync(0xffffffffu, m);
    if (l == 0) g_q_active[b] = (bal == 0u) ? 1 : 0;
}

// ---------------------------------------------------------------------------
// Kernel 3: score kernel. Block = (o, b). 256 threads = 8 warps.
// Warp w owns i rows [4w,4w+4); lane l owns j in {4l..4l+3, 128+4l..128+4l+3}.
// k streamed through smem in 32-d transposed chunks kt[d][j] (conflict-free).
// ---------------------------------------------------------------------------
__global__ __launch_bounds__(256, 3)
void score_kernel(const void* __restrict__ k_mask,
                  const float* __restrict__ logit_scale,
                  float* __restrict__ out) {
    const int o   = blockIdx.x;
    const int b   = blockIdx.y;
    const int tid = threadIdx.x;

    if (!g_q_active[b]) {                 // whole row is exactly 0 (lse = -inf)
        if (tid == 0) out[b * O_ + o] = 0.0f;
        return;
    }

    extern __shared__ float smem[];
    float* q_s  = smem;                   // 32*128 = 4096 f
    float* kt_s = q_s + LQ * D_;          // 32*256 = 8192 f (chunk, [d_local][j])
    float* w_s  = kt_s + 32 * LK;         // 256 f   (k validity weights)
    float* red  = w_s + LK;               // 8 f

    // Stage q tile [32][128]
    const float4* q4 = (const float4*)(g_qn + (size_t)b * LQ * D_);
    #pragma unroll
    for (int it = 0; it < 4; it++)
        ((float4*)q_s)[it * 256 + tid] = q4[it * 256 + tid];

    // k validity weights
    {
        int mode = g_mask_mode;
        w_s[tid] = mask_at(k_mask, o * LK + tid, mode) ? 0.0f : 1.0f;
    }

    const int w = tid >> 5, l = tid & 31;
    float acc[4][8];
    #pragma unroll
    for (int ii = 0; ii < 4; ii++)
        #pragma unroll
        for (int jj = 0; jj < 8; jj++) acc[ii][jj] = 0.0f;

    const float4* kr4 = (const float4*)(g_kn + (size_t)o * LK * D_); // [j][d/4]

    #pragma unroll 1
    for (int c = 0; c < 4; c++) {         // 4 chunks of 32 d
        __syncthreads();
        // Load+transpose chunk: thread tid handles j=tid, 8 float4 along d.
        #pragma unroll
        for (int d4 = 0; d4 < 8; d4++) {
            float4 v = kr4[tid * (D_ / 4) + c * 8 + d4];
            int dl = d4 * 4;
            kt_s[(dl + 0) * LK + tid] = v.x;
            kt_s[(dl + 1) * LK + tid] = v.y;
            kt_s[(dl + 2) * LK + tid] = v.z;
            kt_s[(dl + 3) * LK + tid] = v.w;
        }
        __syncthreads();

        const float4* kt4 = (const float4*)kt_s;
        #pragma unroll 4
        for (int d = 0; d < 32; d++) {
            float4 k0 = kt4[d * 64 + l];
            float4 k1 = kt4[d * 64 + 32 + l];
            float qv[4];
            #pragma unroll
            for (int ii = 0; ii < 4; ii++)
                qv[ii] = q_s[(w * 4 + ii) * D_ + c * 32 + d];   // broadcast
            #pragma unroll
            for (int ii = 0; ii < 4; ii++) {
                acc[ii][0] = fmaf(qv[ii], k0.x, acc[ii][0]);
                acc[ii][1] = fmaf(qv[ii], k0.y, acc[ii][1]);
                acc[ii][2] = fmaf(qv[ii], k0.z, acc[ii][2]);
                acc[ii][3] = fmaf(qv[ii], k0.w, acc[ii][3]);
                acc[ii][4] = fmaf(qv[ii], k1.x, acc[ii][4]);
                acc[ii][5] = fmaf(qv[ii], k1.y, acc[ii][5]);
                acc[ii][6] = fmaf(qv[ii], k1.z, acc[ii][6]);
                acc[ii][7] = fmaf(qv[ii], k1.w, acc[ii][7]);
            }
        }
    }

    // Epilogue: lse_i = log( sum_j w_j * exp(12*S_ij) ); block-sum over i.
    float4 w0 = ((const float4*)w_s)[l];
    float4 w1 = ((const float4*)w_s)[32 + l];
    const float A = 12.0f;
    float lsum = 0.0f;
    #pragma unroll
    for (int ii = 0; ii < 4; ii++) {
        float p = w0.x * __expf(A * acc[ii][0]) + w0.y * __expf(A * acc[ii][1])
                + w0.z * __expf(A * acc[ii][2]) + w0.w * __expf(A * acc[ii][3])
                + w1.x * __expf(A * acc[ii][4]) + w1.y * __expf(A * acc[ii][5])
                + w1.z * __expf(A * acc[ii][6]) + w1.w * __expf(A * acc[ii][7]);
        #pragma unroll
        for (int of = 16; of; of >>= 1) p += __shfl_xor_sync(0xffffffffu, p, of);
        if (l == 0) lsum += __logf(p);    // log(0) = -inf handled at the end
    }
    if (l == 0) red[w] = lsum;
    __syncthreads();

    if (tid == 0) {
        float t = 0.0f;
        #pragma unroll
        for (int i = 0; i < 8; i++) t += red[i];
        float s = t * (1.0f / 12.0f);
        s = s / (sqrtf((float)(LQ * LK)) + 1e-6f);
        float sc = fminf(expf(logit_scale[0]), 100.0f);
        s *= sc;
        if (!isfinite(s)) s = 0.0f;
        out[b * O_ + o] = s;
    }
}

// ---------------------------------------------------------------------------
extern "C" void kernel_launch(void* const* d_in, const int* in_sizes, int n_in,
                              void* d_out, int out_size) {
    const float* q  = (const float*)d_in[0];
    const float* k  = (const float*)d_in[1];
    const void*  qm = d_in[2];
    const void*  km = d_in[3];
    const float* ls = (const float*)d_in[4];
    float* out = (float*)d_out;

    // 0) sniff mask dtype (reads only first 2048 bytes of q_mask — safe)
    detect_mask_kernel<<<1, 32>>>((const unsigned int*)qm);

    // 1) normalize (warp per row): rows = 64*32 + 128*256 = 34816, 8 warps/blk
    {
        int nrows = B_ * LQ + O_ * LK;
        int blocks = (nrows + 7) / 8;
        norm_kernel<<<blocks, 256>>>(q, k);
    }
    // 2) per-batch active flags
    qactive_kernel<<<B_, 32>>>(qm);

    // 3) score
    {
        const int smem_bytes = (LQ * D_ + 32 * LK + LK + 8) * (int)sizeof(float);
        cudaFuncSetAttribute(score_kernel,
                             cudaFuncAttributeMaxDynamicSharedMemorySize,
                             smem_bytes);
        dim3 grid(O_, B_);
        score_kernel<<<grid, 256, smem_bytes>>>(km, ls, out);
    }
}